// round 9
// baseline (speedup 1.0000x reference)
#include <cuda_runtime.h>
#include <cstdint>

#define PB 32
#define PS 1024
#define PNODE 256
#define PDEP 64
#define PR 50
#define PL 16
#define PE 128
#define PF 320
#define NEDGE (PB * PE)     // 4096
#define NTOT (PL * NEDGE)   // 65536
#define MAXCHUNK 640
#define PREPB 64
#define MAXSLOT 288

// chain: block = (batch, k-quarter): 128 blocks, 1/SM
#define CH_BLOCKS (PB * 4)
#define WRSTR 1032           // floats per rel in Ws: 64*16 + 8 pad (conflict stagger)

// ---------------- scratch --------------------------------------------------
__device__ float g_child[PB * PS * PDEP];
__device__ float g_pmsg[PL * NEDGE * PDEP];
__device__ int   g_gsort[NTOT];
__device__ int   g_gcnt[PR];
__device__ int   g_gbase[PR + 1];
__device__ int   g_gcur[PR];
__device__ int   g_chunk_rel[MAXCHUNK];
__device__ int   g_chunk_start[MAXCHUNK];
__device__ int   g_chunk_ne[MAXCHUNK];
__device__ int   g_nchunks;
__device__ unsigned int g_ticket;
__device__ int   g_slots[PB * PL * MAXSLOT];     // (r<<7)|e, bit15 = pad
__device__ int   g_nslot[PB * PL];
__device__ int   g_hkey[NTOT];
__device__ int   g_hidx[NTOT];
__device__ unsigned int g_cbar[PB * 32];
__device__ unsigned int g_pbar;

// ---------------- f32x2 helpers -------------------------------------------
__device__ __forceinline__ void fma2(unsigned long long& acc,
                                     unsigned long long a, unsigned long long b) {
    asm("fma.rn.f32x2 %0, %1, %2, %0;" : "+l"(acc) : "l"(a), "l"(b));
}
__device__ __forceinline__ unsigned long long pack2(float x, float y) {
    unsigned long long v;
    asm("mov.b64 %0, {%1,%2};" : "=l"(v) : "r"(__float_as_uint(x)), "r"(__float_as_uint(y)));
    return v;
}
__device__ __forceinline__ void unpack2(unsigned long long v, float& x, float& y) {
    unsigned int lo, hi;
    asm("mov.b64 {%0,%1}, %2;" : "=r"(lo), "=r"(hi) : "l"(v));
    x = __uint_as_float(lo); y = __uint_as_float(hi);
}
__device__ __forceinline__ float hsum2(unsigned long long v) {
    float x, y; unpack2(v, x, y); return x + y;
}

// ---------------- launch 0: init -------------------------------------------
__global__ void k_init(const float* __restrict__ ctx, float* __restrict__ out) {
    if (blockIdx.x == 0) {
        if (threadIdx.x == 0) { g_ticket = 0; g_pbar = 0; }
        if (threadIdx.x < PR) g_gcnt[threadIdx.x] = 0;
        for (int i = threadIdx.x; i < PB * 32; i += blockDim.x) g_cbar[i] = 0;
    }
    const int64_t n_ctx = (int64_t)PB * PS * (PNODE / 4);
    const int64_t n_chd = (int64_t)PB * PS * (PDEP / 4);
    const int64_t total = n_ctx + n_chd;
    int64_t stride = (int64_t)gridDim.x * blockDim.x;
    for (int64_t i = (int64_t)blockIdx.x * blockDim.x + threadIdx.x; i < total; i += stride) {
        if (i < n_ctx) {
            int64_t row = i >> 6, d4 = i & 63;
            float4 v = ((const float4*)ctx)[i];
            *(float4*)&out[row * PF + d4 * 4] = v;
        } else {
            ((float4*)g_child)[i - n_ctx] = make_float4(0.f, 0.f, 0.f, 0.f);
        }
    }
}

// ---------------- prep barrier ---------------------------------------------
__device__ __forceinline__ void psync(int* pc) {
    __syncthreads();
    (*pc)++;
    if (threadIdx.x == 0) {
        __threadfence();
        atomicAdd(&g_pbar, 1);
        unsigned int target = (unsigned int)(PREPB * (*pc));
        while (*(volatile unsigned int*)&g_pbar < target) { }
        __threadfence();
    }
    __syncthreads();
}

// ---------------- launch 1: preprocessing ----------------------------------
__global__ void __launch_bounds__(256, 2)
k_prep(const int* __restrict__ rels, const int* __restrict__ heads) {
    int bid = blockIdx.x;
    int tid = threadIdx.x;
    int w = tid >> 5, lane = tid & 31;
    __shared__ int cnt[PR];
    __shared__ int hs2[2][128];
    __shared__ int srel[8][128];
    __shared__ int sb[PR], sch[PR];
    int pc = 0;

    // --- A1: global rel histogram ---
    if (tid < PR) cnt[tid] = 0;
    __syncthreads();
    int ebase = bid * 1024;
    #pragma unroll
    for (int t = 0; t < 4; t++)
        atomicAdd(&cnt[rels[ebase + tid + t * 256]], 1);
    __syncthreads();
    if (tid < PR && cnt[tid] > 0) atomicAdd(&g_gcnt[tid], cnt[tid]);

    // --- A2: per (b,l) padded rel-quad slot lists ---
    {
        int task = bid * 8 + w;           // 0..511 = b*PL + l
        int b = task >> 4, l = task & 15;
        #pragma unroll
        for (int t = 0; t < 4; t++)
            srel[w][lane + 32 * t] = rels[b * (PL * PE) + l * PE + lane + 32 * t];
        __syncwarp();
        int c0 = 0, c1 = 0;
        int r1 = lane + 32;
        for (int j = 0; j < PE; j++) {
            int rv = srel[w][j];
            c0 += (rv == lane);
            c1 += (rv == r1);
        }
        int p0 = (c0 + 3) & ~3;
        int p1 = (r1 < PR) ? ((c1 + 3) & ~3) : 0;
        int s0 = p0, s1 = p1;
        #pragma unroll
        for (int o = 1; o < 32; o <<= 1) {
            int x0 = __shfl_up_sync(0xffffffffu, s0, o);
            int x1 = __shfl_up_sync(0xffffffffu, s1, o);
            if (lane >= o) { s0 += x0; s1 += x1; }
        }
        int tot0 = __shfl_sync(0xffffffffu, s0, 31);
        int tot1 = __shfl_sync(0xffffffffu, s1, 31);
        int off0 = s0 - p0;
        int off1 = tot0 + s1 - p1;
        int* dst = &g_slots[task * MAXSLOT];
        int o0 = off0;
        for (int j = 0; j < PE; j++)
            if (srel[w][j] == lane) dst[o0++] = (lane << 7) | j;
        while (o0 < off0 + p0) dst[o0++] = (lane << 7) | 0x8000;
        if (p1 > 0) {
            int o1 = off1;
            for (int j = 0; j < PE; j++)
                if (srel[w][j] == r1) dst[o1++] = (r1 << 7) | j;
            while (o1 < off1 + p1) dst[o1++] = (r1 << 7) | 0x8000;
        }
        if (lane == 31) g_nslot[task] = tot0 + tot1;
    }

    // --- A3: head rank-sort ---
    #pragma unroll
    for (int t = 0; t < 4; t++) {
        int task = bid * 8 + t * 2 + (tid >> 7);
        int l = task >> 5, b = task & 31;
        int e = tid & 127;
        int h = heads[b * (PL * PE) + l * PE + e];
        hs2[tid >> 7][e] = h;
        __syncthreads();
        int rank = 0;
        #pragma unroll 8
        for (int o = 0; o < PE; o++) {
            int ho = hs2[tid >> 7][o];
            rank += (ho < h) || (ho == h && o < e);
        }
        int base = l * NEDGE + b * PE;
        g_hkey[base + rank] = h;
        g_hidx[base + rank] = e;
        __syncthreads();
    }

    psync(&pc);

    // --- B: prefix + chunk worklist (block 0) ---
    if (bid == 0) {
        if (tid == 0) {
            int s = 0, nc = 0;
            for (int r = 0; r < PR; r++) {
                sb[r] = s;
                sch[r] = nc;
                int c = g_gcnt[r];
                s += c;
                nc += (c + 127) >> 7;
            }
            g_gbase[PR] = s;
            g_nchunks = nc;
        }
        __syncthreads();
        if (tid < PR) {
            int b0 = sb[tid];
            g_gbase[tid] = b0;
            g_gcur[tid] = b0;
            int c = g_gcnt[tid];
            int nc0 = sch[tid];
            for (int o = 0, k = 0; o < c; o += 128, k++) {
                g_chunk_rel[nc0 + k] = tid;
                g_chunk_start[nc0 + k] = b0 + o;
                g_chunk_ne[nc0 + k] = min(128, c - o);
            }
        }
    }

    psync(&pc);

    // --- C: global scatter with range reservation ---
    __shared__ int rbase[PR], rcur[PR];
    if (tid < PR) rcur[tid] = 0;
    __syncthreads();
    if (tid < PR) rbase[tid] = (cnt[tid] > 0) ? atomicAdd(&g_gcur[tid], cnt[tid]) : 0;
    __syncthreads();
    #pragma unroll
    for (int t = 0; t < 4; t++) {
        int idx = ebase + tid + t * 256;
        int r = rels[idx];
        int pos = rbase[r] + atomicAdd(&rcur[r], 1);
        int b = idx >> 11, l = (idx >> 7) & 15, e = idx & 127;
        g_gsort[pos] = (l << 12) | (b << 7) | e;
    }
}

// ---------------- launch 2: pmsg (ticket-queue, unchanged core) ------------
#define PM_STRIDE 260
#define PM_SMEM ((64 * PM_STRIDE + 128 * PM_STRIDE) * (int)sizeof(float))

__global__ void __launch_bounds__(256, 1)
k_pmsg(const float* __restrict__ ctx, const float* __restrict__ W,
       const int* __restrict__ tails) {
    extern __shared__ float sm[];
    float* Ws = sm;
    float* Fs = sm + 64 * PM_STRIDE;
    __shared__ int seid[128];
    __shared__ int stail[128];
    __shared__ int s_chunk;
    int tid = threadIdx.x;

    while (true) {
        if (tid == 0) s_chunk = atomicAdd(&g_ticket, 1);
        __syncthreads();
        int c = s_chunk;
        if (c >= g_nchunks) break;
        int r = g_chunk_rel[c];
        int start = g_chunk_start[c];
        int ne = g_chunk_ne[c];

        if (tid < 128) {
            int v = (tid < ne) ? g_gsort[start + tid] : -1;
            seid[tid] = v;
            int tnode = 0;
            if (v >= 0) {
                int b = (v >> 7) & 31, l = v >> 12, e = v & 127;
                tnode = b * PS + tails[b * (PL * PE) + l * PE + e];
            }
            stail[tid] = tnode;
        }
        const float* Wg = W + (int64_t)r * PDEP * PF;
        #pragma unroll
        for (int t = 0; t < 16; t++) {
            int idx = tid + t * 256;
            int k = idx >> 6, cc = idx & 63;
            *(float4*)&Ws[k * PM_STRIDE + cc * 4] = *(const float4*)&Wg[k * PF + cc * 4];
        }
        __syncthreads();

        #pragma unroll
        for (int t = 0; t < 32; t++) {
            int idx = tid + t * 256;
            int row = idx >> 6, cc = idx & 63;
            float4 v = make_float4(0.f, 0.f, 0.f, 0.f);
            if (seid[row] >= 0)
                v = *(const float4*)&ctx[(int64_t)stail[row] * PNODE + cc * 4];
            *(float4*)&Fs[row * PM_STRIDE + cc * 4] = v;
        }
        __syncthreads();

        int eg = tid & 31;
        int kg = tid >> 5;
        unsigned long long acc[4][8];
        #pragma unroll
        for (int i = 0; i < 4; i++)
            #pragma unroll
            for (int j = 0; j < 8; j++) acc[i][j] = 0ull;

        #pragma unroll 4
        for (int d = 0; d < PNODE; d += 4) {
            ulonglong2 w[8];
            #pragma unroll
            for (int j = 0; j < 8; j++)
                w[j] = *(const ulonglong2*)&Ws[(kg + 8 * j) * PM_STRIDE + d];
            #pragma unroll
            for (int i = 0; i < 4; i++) {
                ulonglong2 f = *(const ulonglong2*)&Fs[(eg + 32 * i) * PM_STRIDE + d];
                #pragma unroll
                for (int j = 0; j < 8; j++) {
                    fma2(acc[i][j], f.x, w[j].x);
                    fma2(acc[i][j], f.y, w[j].y);
                }
            }
        }

        #pragma unroll
        for (int i = 0; i < 4; i++) {
            int v = seid[eg + 32 * i];
            if (v >= 0) {
                int l = v >> 12, edge = v & 4095;
                float* dst = &g_pmsg[((int64_t)l * NEDGE + edge) * PDEP];
                #pragma unroll
                for (int j = 0; j < 8; j++)
                    dst[kg + 8 * j] = hsum2(acc[i][j]);
            }
        }
        __syncthreads();
    }
}

// ---------------- launch 3: chain: block = (batch, k-quarter) --------------
// Ws: 50 rels x [64 d][16 k] (+8 pad) resident all 16 layers.
// Ms: this batch's msgs for own 16 k. ONE 4-arrival barrier per layer.
#define CH_SMEM ((PR * WRSTR + PE * 16) * (int)sizeof(float))   // 214592 B

__global__ void __launch_bounds__(256, 1)
k_chain(const float* __restrict__ W, const int* __restrict__ tails,
        float* __restrict__ out) {
    extern __shared__ float sm[];
    float* Ws = sm;                     // [PR][WRSTR]
    float* Ms = sm + PR * WRSTR;        // [128][16] msgs (own k-quarter)
    __shared__ int s_slot[MAXSLOT];
    __shared__ int s_tn[MAXSLOT];
    __shared__ int s_hk[128];
    __shared__ int s_hx[128];
    __shared__ int s_nslot;

    int bid = blockIdx.x;
    int b = bid >> 2, kq = bid & 3;
    int tid = threadIdx.x;
    int e_t = tid & 127, kh = tid >> 7;   // phase-1: edge slot-lane, k-half (8 k)

    // stage W k-quarter, transposed to [r][d][16k]
    for (int idx = tid; idx < PR * 16 * 16; idx += 256) {
        int r = idx >> 8, rem = idx & 255;
        int k = rem >> 4, d4 = rem & 15;
        float4 v = *(const float4*)&W[((int64_t)r * PDEP + kq * 16 + k) * PF + PNODE + d4 * 4];
        Ws[r * WRSTR + (d4 * 4 + 0) * 16 + k] = v.x;
        Ws[r * WRSTR + (d4 * 4 + 1) * 16 + k] = v.y;
        Ws[r * WRSTR + (d4 * 4 + 2) * 16 + k] = v.z;
        Ws[r * WRSTR + (d4 * 4 + 3) * 16 + k] = v.w;
    }
    // stage layer-0 head data
    if (tid < 128) {
        s_hk[tid] = __ldg(&g_hkey[b * PE + tid]);
        s_hx[tid] = __ldg(&g_hidx[b * PE + tid]);
    }
    __syncthreads();

    unsigned int* bar = &g_cbar[b * 32];
    float* childb = &g_child[b * PS * PDEP];
    int calls = 0;

    for (int l = 0; l < PL; l++) {
        // ================= phase 1 (l > 0): msgs for own k-quarter =========
        if (l > 0) {
            int nslot = s_nslot;
            for (int t0 = 0; t0 < nslot; t0 += 128) {
                int sidx = t0 + e_t;
                int sv = (sidx < nslot) ? s_slot[sidx] : -1;
                bool real = (sv >= 0) && !(sv & 0x8000);
                int r = (sv < 0) ? 0 : ((sv >> 7) & 63);
                // load child row (16 float4, one MLP burst) + pmsg (own 8 k)
                float4 f[16];
                float2 pm0 = make_float2(0.f, 0.f), pm1 = make_float2(0.f, 0.f);
                if (real) {
                    const float4* cp = (const float4*)&childb[s_tn[sidx] * PDEP];
                    #pragma unroll
                    for (int j = 0; j < 16; j++) f[j] = __ldcg(&cp[j]);
                    const float4* pp = (const float4*)&g_pmsg[
                        ((int64_t)l * NEDGE + b * PE + (sv & 127)) * PDEP + kq * 16 + kh * 8];
                    float4 p0 = __ldcg(&pp[0]), p1 = __ldcg(&pp[1]);
                    pm0 = make_float2(p0.x, p0.y);  pm1 = make_float2(p0.z, p0.w);
                    float2 q0 = make_float2(p1.x, p1.y), q1 = make_float2(p1.z, p1.w);
                    // accumulate into 4 k-pairs
                    unsigned long long acc0 = 0ull, acc1 = 0ull, acc2 = 0ull, acc3 = 0ull;
                    const float* wp = &Ws[r * WRSTR + kh * 8];
                    #pragma unroll 8
                    for (int d4 = 0; d4 < 16; d4++) {
                        float4 cv = f[d4];
                        ulonglong2 wa = *(const ulonglong2*)&wp[(d4 * 4 + 0) * 16];
                        ulonglong2 wb = *(const ulonglong2*)&wp[(d4 * 4 + 1) * 16];
                        ulonglong2 wc = *(const ulonglong2*)&wp[(d4 * 4 + 2) * 16];
                        ulonglong2 wd = *(const ulonglong2*)&wp[(d4 * 4 + 3) * 16];
                        unsigned long long cx = pack2(cv.x, cv.x);
                        unsigned long long cy = pack2(cv.y, cv.y);
                        unsigned long long cz = pack2(cv.z, cv.z);
                        unsigned long long cw = pack2(cv.w, cv.w);
                        fma2(acc0, wa.x, cx); fma2(acc1, wa.y, cx);
                        fma2(acc0, wb.x, cy); fma2(acc1, wb.y, cy);
                        fma2(acc0, wc.x, cz); fma2(acc1, wc.y, cz);
                        fma2(acc0, wd.x, cw); fma2(acc1, wd.y, cw);
                        // second pair group (k +4..7)
                        ulonglong2 wa2 = *(const ulonglong2*)&wp[(d4 * 4 + 0) * 16 + 4];
                        ulonglong2 wb2 = *(const ulonglong2*)&wp[(d4 * 4 + 1) * 16 + 4];
                        ulonglong2 wc2 = *(const ulonglong2*)&wp[(d4 * 4 + 2) * 16 + 4];
                        ulonglong2 wd2 = *(const ulonglong2*)&wp[(d4 * 4 + 3) * 16 + 4];
                        fma2(acc2, wa2.x, cx); fma2(acc3, wa2.y, cx);
                        fma2(acc2, wb2.x, cy); fma2(acc3, wb2.y, cy);
                        fma2(acc2, wc2.x, cz); fma2(acc3, wc2.y, cz);
                        fma2(acc2, wd2.x, cw); fma2(acc3, wd2.y, cw);
                    }
                    float a0, a1, a2, a3, a4, a5, a6, a7;
                    unpack2(acc0, a0, a1); unpack2(acc1, a2, a3);
                    unpack2(acc2, a4, a5); unpack2(acc3, a6, a7);
                    int e = sv & 127;
                    float4 o0 = make_float4(a0 + pm0.x, a1 + pm0.y, a2 + pm1.x, a3 + pm1.y);
                    float4 o1 = make_float4(a4 + q0.x, a5 + q0.y, a6 + q1.x, a7 + q1.y);
                    *(float4*)&Ms[e * 16 + kh * 8] = o0;
                    *(float4*)&Ms[e * 16 + kh * 8 + 4] = o1;
                }
            }
        } else {
            // layer 0: msgs = pmsg (own k-quarter slice)
            #pragma unroll
            for (int t = 0; t < 2; t++) {
                int idx = tid + t * 256;      // 512 float4
                int e = idx >> 2, c4 = idx & 3;
                float4 v = __ldcg((const float4*)&g_pmsg[
                    ((int64_t)(b * PE + e)) * PDEP + kq * 16 + c4 * 4]);
                *(float4*)&Ms[e * 16 + c4 * 4] = v;
            }
        }
        __syncthreads();

        // ---- prefetch next layer's static data (latency hidden by phase 2) --
        int pf_sv0 = -1, pf_sv1 = -1, pf_tn0 = 0, pf_tn1 = 0;
        int pf_hk = 0, pf_hx = 0, pf_len = 0;
        if (l + 1 < PL) {
            pf_len = __ldg(&g_nslot[b * PL + l + 1]);
            if (tid < pf_len) {
                int sv = __ldg(&g_slots[(b * PL + l + 1) * MAXSLOT + tid]);
                pf_sv0 = sv;
                if (!(sv & 0x8000))
                    pf_tn0 = __ldg(&tails[b * (PL * PE) + (l + 1) * PE + (sv & 127)]);
            }
            int idx2 = tid + 256;
            if (idx2 < pf_len) {
                int sv = __ldg(&g_slots[(b * PL + l + 1) * MAXSLOT + idx2]);
                pf_sv1 = sv;
                if (!(sv & 0x8000))
                    pf_tn1 = __ldg(&tails[b * (PL * PE) + (l + 1) * PE + (sv & 127)]);
            }
            if (tid < 128) {
                pf_hk = __ldg(&g_hkey[(l + 1) * NEDGE + b * PE + tid]);
                pf_hx = __ldg(&g_hidx[(l + 1) * NEDGE + b * PE + tid]);
            }
        }

        // ================= phase 2: segment average (smem) ==================
        {
            int wid = tid >> 5, lane = tid & 31;
            int sub = lane >> 4, kl = lane & 15;
            #pragma unroll
            for (int it = 0; it < 8; it++) {
                int p = wid * 16 + it * 2 + sub;
                int h = s_hk[p];
                if (p > 0 && s_hk[p - 1] == h) continue;
                int len = 1;
                while (p + len < PE && s_hk[p + len] == h) len++;
                float s = 0.f;
                for (int j = 0; j < len; j++)
                    s += Ms[s_hx[p + j] * 16 + kl];
                __stcg(&childb[h * PDEP + kq * 16 + kl], s * (1.f / (float)len));
            }
        }

        if (l + 1 < PL) {
            // fence + arrive
            __syncthreads();
            calls++;
            if (tid == 0) { __threadfence(); atomicAdd(bar, 1); }
            // gap: commit prefetched data (not read by any pre-arrive phase)
            if (tid < MAXSLOT) { s_slot[tid] = pf_sv0; s_tn[tid] = pf_tn0; }
            int idx2 = tid + 256;
            if (idx2 < MAXSLOT) { s_slot[idx2] = pf_sv1; s_tn[idx2] = pf_tn1; }
            if (tid < 128) { s_hk[tid] = pf_hk; s_hx[tid] = pf_hx; }
            if (tid == 0) s_nslot = pf_len;
            // wait
            if (tid == 0) {
                unsigned int target = (unsigned int)(4 * calls);
                while (*(volatile unsigned int*)bar < target) { }
                __threadfence();
            }
            __syncthreads();
        }
    }

    // ---- out write: own (batch, k-quarter) slice; no inter-block dep ----
    __syncthreads();
    #pragma unroll
    for (int t = 0; t < 16; t++) {
        int idx = tid + t * 256;              // 4096 float4
        int srow = idx >> 2, c4 = idx & 3;
        const float* c = &childb[srow * PDEP + kq * 16 + c4 * 4];
        float4 v;
        v.x = __ldcg(&c[0]); v.y = __ldcg(&c[1]);
        v.z = __ldcg(&c[2]); v.w = __ldcg(&c[3]);
        *(float4*)&out[((int64_t)(b * PS + srow)) * PF + PNODE + kq * 16 + c4 * 4] = v;
    }
}

// ---------------------------------------------------------------------------
extern "C" void kernel_launch(void* const* d_in, const int* in_sizes, int n_in,
                              void* d_out, int out_size) {
    const float* ctx   = (const float*)d_in[0];
    const float* W     = (const float*)d_in[1];
    const int*   heads = (const int*)d_in[2];
    const int*   tails = (const int*)d_in[3];
    const int*   rels  = (const int*)d_in[4];
    float*       out   = (float*)d_out;

    cudaFuncSetAttribute(k_pmsg, cudaFuncAttributeMaxDynamicSharedMemorySize, PM_SMEM);
    cudaFuncSetAttribute(k_chain, cudaFuncAttributeMaxDynamicSharedMemorySize, CH_SMEM);

    k_init<<<2048, 256>>>(ctx, out);                  // launch 0
    k_prep<<<PREPB, 256>>>(rels, heads);              // launch 1
    k_pmsg<<<148, 256, PM_SMEM>>>(ctx, W, tails);     // launch 2
    k_chain<<<CH_BLOCKS, 256, CH_SMEM>>>(W, tails, out); // launch 3
}